// round 13
// baseline (speedup 1.0000x reference)
#include <cuda_runtime.h>
#include <cuda_fp16.h>
#include <cstdint>
#include <math.h>

#define BB 128
#define TT 1024
#define HH 512
#define NCTA 99
#define NTHR 512
#define RING 4

// smem: per-wg 3 A-buffers (128 x 144B) + persistent W + flags
#define ABYTES 18432
#define OFF_W  (2 * 3 * ABYTES)            // 110592
#define OFF_F  (OFF_W + 48 * 2064)         // 209664
#define SMEM_BYTES (OFF_F + 64)            // 209728

// ------------------------- persistent device state ---------------------------
__device__ float g_ig0[65 * 1536];                        // layer0 igates + bias
__device__ __align__(16) __half g_hA[3][RING][BB * HH];   // fp16 h ring [lay][slot]
__device__ __align__(16) __half g_wf16s[6][1536 * 512];   // fp16 weights [part]
__device__ unsigned g_prod[3];   // 32 * steps completed per layer
__device__ unsigned g_cons[3];   // external consumptions of layer l's output

// ------------------------------ helpers --------------------------------------
__device__ __forceinline__ float sigm(float x) { return 1.f / (1.f + __expf(-x)); }
__device__ __forceinline__ uint32_t smem_u32(const void* p) {
    uint32_t a;
    asm("{ .reg .u64 t; cvta.to.shared.u64 t, %1; cvt.u32.u64 %0, t; }" : "=r"(a) : "l"(p));
    return a;
}
__device__ __forceinline__ void ldsm4(uint32_t a, uint32_t& r0, uint32_t& r1,
                                      uint32_t& r2, uint32_t& r3) {
    asm volatile("ldmatrix.sync.aligned.m8n8.x4.shared.b16 {%0,%1,%2,%3}, [%4];"
                 : "=r"(r0), "=r"(r1), "=r"(r2), "=r"(r3) : "r"(a));
}
__device__ __forceinline__ void ldsm2(uint32_t a, uint32_t& r0, uint32_t& r1) {
    asm volatile("ldmatrix.sync.aligned.m8n8.x2.shared.b16 {%0,%1}, [%2];"
                 : "=r"(r0), "=r"(r1) : "r"(a));
}
__device__ __forceinline__ void mma4(float* d, uint32_t a0, uint32_t a1, uint32_t a2,
                                     uint32_t a3, uint32_t b0, uint32_t b1) {
    asm volatile("mma.sync.aligned.m16n8k16.row.col.f32.f16.f16.f32 "
                 "{%0,%1,%2,%3},{%4,%5,%6,%7},{%8,%9},{%0,%1,%2,%3};"
                 : "+f"(d[0]), "+f"(d[1]), "+f"(d[2]), "+f"(d[3])
                 : "r"(a0), "r"(a1), "r"(a2), "r"(a3), "r"(b0), "r"(b1));
}
__device__ __forceinline__ void cp16(uint32_t dst, const void* src) {
    asm volatile("cp.async.cg.shared.global [%0], [%1], 16;" :: "r"(dst), "l"(src));
}
#define CP_COMMIT() asm volatile("cp.async.commit_group;" ::: "memory")
#define CP_WAIT1()  asm volatile("cp.async.wait_group 1;" ::: "memory")
#define CP_WAIT0()  asm volatile("cp.async.wait_group 0;" ::: "memory")
#define WG_BAR(id)  asm volatile("bar.sync %0, 256;" :: "r"(id) : "memory")

// one poller per warpgroup; release via named barrier
__device__ __forceinline__ void wg_wait(volatile unsigned* p, unsigned target,
                                        bool poller, int barid) {
    if (poller) { while (*p < target) { } }
    WG_BAR(barid);
}

// ------------------------------ prep kernels ---------------------------------
__global__ void k_zero() {
    long i = (long)blockIdx.x * blockDim.x + threadIdx.x;
    __half* ph = &g_hA[0][0][0];
    long nh = 3L * RING * BB * HH;
    for (long j = i; j < nh; j += (long)gridDim.x * blockDim.x) ph[j] = __float2half(0.f);
    if (i < 3) { g_prod[i] = 0u; g_cons[i] = 0u; }
}

__global__ void k_ig0(const float* __restrict__ emb, const float* __restrict__ w_ih,
                      const float* __restrict__ bias) {
    int idx = blockIdx.x * blockDim.x + threadIdx.x;
    if (idx >= 65 * 1536) return;
    int tok = idx / 1536, j = idx - tok * 1536;
    const float* e = emb + tok * HH;
    const float* w = w_ih + (long)j * HH;
    float acc = bias[j];
    #pragma unroll 8
    for (int k = 0; k < HH; ++k) acc += e[k] * w[k];
    g_ig0[idx] = acc;
}

__global__ void k_prepw(const float* __restrict__ w_ih, const float* __restrict__ w_hh,
                        const float* __restrict__ w_out) {
    long idx = (long)blockIdx.x * 256 + threadIdx.x;     // 6 * 1536 * 512
    if (idx >= 6L * 1536 * 512) return;
    int k = (int)(idx & 511);
    long r = idx >> 9;
    int row = (int)(r % 1536);
    int part = (int)(r / 1536);
    float v = 0.f;
    if (part == 0)      v = w_hh[(long)row * 512 + k];
    else if (part == 1) v = w_ih[(1536L + row) * 512 + k];
    else if (part == 2) v = w_hh[(1536L + row) * 512 + k];
    else if (part == 3) v = w_ih[(2L * 1536 + row) * 512 + k];
    else if (part == 4) v = w_hh[(2L * 1536 + row) * 512 + k];
    else if (row < 65)  v = w_out[(long)row * 512 + k];
    g_wf16s[part][(long)row * 512 + k] = __float2half(v);
}

// ------------------------------ GEMM core ------------------------------------
// One warpgroup's K=512 GEMM: 8 chunks of 64 cols, private 3-buffer cp.async
// pipeline, per-wg named barrier. W persistent in smem (kcolB selects x/h part).
// MODE 0: 6 tiles rows 0-47 (3x ldsm4)         [L1/L2 split-K wg]
// MODE 1: 3 tiles rows rowbase..+24 (x4 + x2)  [L0 wg]
// MODE 2: 2 tiles rows 0-15 (x4)               [out wg0]
// MODE 3: 1 tile  rows 16-23 (x2)              [out wg1]
template <int MODE>
__device__ __forceinline__ void gemm_wg(
    const __half* __restrict__ A, uint32_t wbase, uint32_t pitchWB, uint32_t kcolB,
    uint32_t abase, int choff, int rowbase, float (&acc)[6][4], int tid, int barid)
{
    const int ltid = tid & 255;
    const int warpw = (tid >> 5) & 7;
    const int lane = tid & 31;
    const int lr = lane & 7, gq = lane >> 3;
    const uint32_t aoff = (uint32_t)((warpw * 16 + lr + (gq & 1) * 8) * 144
                                     + (gq >> 1) * 16);
    const uint32_t wr0 = (uint32_t)(rowbase + lr + (gq & 1) * 8) * pitchWB;
    const uint32_t wr1 = (uint32_t)(rowbase + 16 + lr + (gq & 1) * 8) * pitchWB;
    const uint32_t wr2 = (uint32_t)(rowbase + 32 + lr + (gq & 1) * 8) * pitchWB;
    const uint32_t wx2 = (uint32_t)(rowbase + 16 + lr) * pitchWB;
    const uint32_t k4 = (uint32_t)((gq >> 1) * 16);
    const uint32_t k2 = (uint32_t)(((lane >> 3) & 1) * 16);

    auto stage = [&](int j) {
        int cg = (j + choff) & 7;
        const __half* s = A + cg * 64;
        uint32_t dst = abase + (uint32_t)(j % 3) * ABYTES;
        #pragma unroll
        for (int i = 0; i < 4; ++i) {
            int e = ltid + i * 256;
            int rr = e >> 3, u = e & 7;
            cp16(dst + (uint32_t)(rr * 144 + u * 16), s + (long)rr * HH + u * 8);
        }
        CP_COMMIT();
    };

    stage(0); stage(1);
    #pragma unroll 1
    for (int j = 0; j < 8; ++j) {
        if (j == 7) CP_WAIT0(); else CP_WAIT1();
        WG_BAR(barid);
        if (j + 2 < 8) stage(j + 2);
        const int cg = (j + choff) & 7;
        const uint32_t kb = kcolB + (uint32_t)cg * 128;
        const uint32_t ab = abase + (uint32_t)(j % 3) * ABYTES;
        #pragma unroll
        for (int ks = 0; ks < 4; ++ks) {
            uint32_t a0, a1, a2, a3;
            ldsm4(ab + aoff + ks * 32, a0, a1, a2, a3);
            const uint32_t kk = kb + ks * 32;
            if (MODE == 0) {
                uint32_t b0, b1, b2, b3;
                ldsm4(wbase + wr0 + kk + k4, b0, b1, b2, b3);
                mma4(acc[0], a0, a1, a2, a3, b0, b2);
                mma4(acc[1], a0, a1, a2, a3, b1, b3);
                ldsm4(wbase + wr1 + kk + k4, b0, b1, b2, b3);
                mma4(acc[2], a0, a1, a2, a3, b0, b2);
                mma4(acc[3], a0, a1, a2, a3, b1, b3);
                ldsm4(wbase + wr2 + kk + k4, b0, b1, b2, b3);
                mma4(acc[4], a0, a1, a2, a3, b0, b2);
                mma4(acc[5], a0, a1, a2, a3, b1, b3);
            } else if (MODE == 1) {
                uint32_t b0, b1, b2, b3, c0, c1;
                ldsm4(wbase + wr0 + kk + k4, b0, b1, b2, b3);
                ldsm2(wbase + wx2 + kk + k2, c0, c1);
                mma4(acc[0], a0, a1, a2, a3, b0, b2);
                mma4(acc[1], a0, a1, a2, a3, b1, b3);
                mma4(acc[2], a0, a1, a2, a3, c0, c1);
            } else if (MODE == 2) {
                uint32_t b0, b1, b2, b3;
                ldsm4(wbase + wr0 + kk + k4, b0, b1, b2, b3);
                mma4(acc[0], a0, a1, a2, a3, b0, b2);
                mma4(acc[1], a0, a1, a2, a3, b1, b3);
            } else {
                uint32_t c0, c1;
                ldsm2(wbase + wx2 + kk + k2, c0, c1);
                mma4(acc[2], a0, a1, a2, a3, c0, c1);
            }
        }
    }
    WG_BAR(barid);    // all warps done; buffers reusable (partial overlay safe)
}

// ------------------------------- main kernel ---------------------------------
__global__ void __launch_bounds__(NTHR, 1) k_main(
    const int* __restrict__ x_seq,
    const float* __restrict__ bias, const float* __restrict__ b_n,
    const float* __restrict__ b_out, float* __restrict__ out)
{
    extern __shared__ unsigned char smem[];
    const uint32_t sbuf = smem_u32(smem);
    const uint32_t wbase = sbuf + OFF_W;
    volatile unsigned* pf = (volatile unsigned*)(smem + OFF_F);
    volatile unsigned* cfl = pf + 1;
    float* partial = (float*)smem;                       // overlays wg0's A bufs
    const int tid = threadIdx.x;
    const int wg = tid >> 8;
    const int ltid = tid & 255;
    const int lane = tid & 31, warpw = (tid >> 5) & 7;
    const int cta = blockIdx.x;
    const uint32_t abase = sbuf + (uint32_t)wg * (3 * ABYTES);
    const bool poller = (ltid == 0);
    const int barid = 1 + wg;

    // ---- role decode: 32 L0 | 32 L1 | 32 L2 | 3 out ----
    int role, lay = 0, n0 = 0, vbase = 0, rows_used, ktot, p0, p1;
    if (cta < 32) {
        role = 0; lay = 0; n0 = cta * 16; rows_used = 48; ktot = 512; p0 = 0; p1 = 0;
    } else if (cta < 64) {
        role = 1; lay = 1; n0 = (cta - 32) * 16; rows_used = 48; ktot = 1024; p0 = 1; p1 = 2;
    } else if (cta < 96) {
        role = 2; lay = 2; n0 = (cta - 64) * 16; rows_used = 48; ktot = 1024; p0 = 3; p1 = 4;
    } else {
        role = 3; lay = 3; vbase = (cta - 96) * 24; rows_used = 24; ktot = 512; p0 = 5; p1 = 5;
    }
    const int pitchWE = ktot + 8;
    const uint32_t pitchWB = (uint32_t)pitchWE * 2;
    const int choff = (cta * 5) & 7;
    const unsigned consC = (lay == 2) ? 3u : 32u;

    // ---- persistent W load + flag init ----
    {
        __half* ws = (__half*)(smem + OFF_W);
        for (int e = tid; e < rows_used * ktot; e += NTHR) {
            int r = e / ktot, k = e - r * ktot;
            int grow;
            if (role < 3) {
                int blk = r >> 3, w = blk / 3, gate = blk % 3;
                grow = gate * HH + n0 + w * 8 + (r & 7);
            } else {
                grow = vbase + r;
                if (grow > 64) grow = 0;
            }
            int part = (k < 512) ? p0 : p1;
            ws[r * pitchWE + k] = g_wf16s[part][(long)grow * 512 + (k & 511)];
        }
    }
    if (tid == 0) { *pf = 0u; *cfl = 0u; }
    __syncthreads();

    const int b0 = warpw * 16 + (lane >> 2);

    if (role == 0) {
        // ---------------- layer 0: both wgs N-split, identical schedule -------
        float hreg[4] = {0.f, 0.f, 0.f, 0.f};
        const int g0 = n0 + wg * 8 + (lane & 3) * 2;
        for (int t = 0; t < TT; ++t) {
            wg_wait(&g_prod[0], 32u * (unsigned)t, poller, barid);
            float acc[6][4] = {};
            gemm_wg<1>(g_hA[0][(t - 1) & 3], wbase, pitchWB, 0, abase, choff,
                       wg * 24, acc, tid, barid);
            if (t >= RING) wg_wait(&g_cons[0], 32u * (unsigned)(t - 3), poller, barid);
            __half* slab = g_hA[0][t & 3];
            #pragma unroll
            for (int bs = 0; bs < 2; ++bs) {
                const int b = b0 + 8 * bs;
                const int tok = __ldg(x_seq + (long)b * TT + t);
                const float* ig = g_ig0 + (long)tok * 1536;
                float hh[2];
                #pragma unroll
                for (int d = 0; d < 2; ++d) {
                    const int g = g0 + d, idx = bs * 2 + d;
                    float r = sigm(__ldg(ig + g) + acc[0][idx]);
                    float z = sigm(__ldg(ig + 512 + g) + acc[1][idx]);
                    float n = tanhf(__ldg(ig + 1024 + g)
                                    + r * (acc[2][idx] + __ldg(b_n + g)));
                    float h = n + z * (hreg[idx] - n);
                    hreg[idx] = h; hh[d] = h;
                }
                __half2 hv; hv.x = __float2half(hh[0]); hv.y = __float2half(hh[1]);
                *(__half2*)(slab + (long)b * HH + g0) = hv;
            }
            __threadfence();
            __syncthreads();
            if (tid == 0) atomicAdd(&g_prod[0], 1u);
        }
    } else if (role == 1 || role == 2) {
        if (wg == 0) {
            // ------------ x-part producer warpgroup --------------------------
            for (int t = 0; t < TT; ++t) {
                if (t >= 1) wg_wait(pf - 1 + 1 == pf ? cfl : cfl, (unsigned)t, poller, 1);
                wg_wait(&g_prod[lay - 1], 32u * (unsigned)(t + 1), poller, 1);
                float acc[6][4] = {};
                gemm_wg<0>(g_hA[lay - 1][t & 3], wbase, pitchWB, 0, abase, choff,
                           0, acc, tid, 1);
                if (tid == 0) atomicAdd(&g_cons[lay - 1], 1u);
                // publish partials into (now idle) own A-buffer region
                #pragma unroll
                for (int i = 0; i < 6; ++i)
                    *(float4*)(partial + ltid * 24 + i * 4) =
                        make_float4(acc[i][0], acc[i][1], acc[i][2], acc[i][3]);
                WG_BAR(1);
                if (tid == 0) *pf = (unsigned)(t + 1);
            }
        } else {
            // ------------ h-part + epilogue warpgroup ------------------------
            float hreg[8] = {0.f, 0.f, 0.f, 0.f, 0.f, 0.f, 0.f, 0.f};
            const float* bl = bias + (long)lay * 1536;
            const float* bnl = b_n + (long)lay * 512;
            for (int t = 0; t < TT; ++t) {
                wg_wait(&g_prod[lay], 32u * (unsigned)t, poller, 2);
                float accH[6][4] = {};
                gemm_wg<0>(g_hA[lay][(t - 1) & 3], wbase, pitchWB, 1024, abase, choff,
                           0, accH, tid, 2);
                wg_wait(pf, (unsigned)(t + 1), poller, 2);
                if (t >= RING) wg_wait(&g_cons[lay], consC * (unsigned)(t - 3), poller, 2);
                __half* slab = g_hA[lay][t & 3];
                const float* myp = partial + ltid * 24;
                #pragma unroll
                for (int cg = 0; cg < 2; ++cg) {
                    const int gb = n0 + cg * 8 + (lane & 3) * 2;
                    #pragma unroll
                    for (int bs = 0; bs < 2; ++bs) {
                        const int b = b0 + 8 * bs;
                        float hh[2];
                        #pragma unroll
                        for (int d = 0; d < 2; ++d) {
                            const int g = gb + d, idx = bs * 2 + d;
                            float ir = myp[(cg * 3 + 0) * 4 + idx] + __ldg(bl + g);
                            float iz = myp[(cg * 3 + 1) * 4 + idx] + __ldg(bl + 512 + g);
                            float in_ = myp[(cg * 3 + 2) * 4 + idx] + __ldg(bl + 1024 + g);
                            float r = sigm(ir + accH[cg * 3 + 0][idx]);
                            float z = sigm(iz + accH[cg * 3 + 1][idx]);
                            float n = tanhf(in_ + r * (accH[cg * 3 + 2][idx] + __ldg(bnl + g)));
                            float h = n + z * (hreg[cg * 4 + idx] - n);
                            hreg[cg * 4 + idx] = h; hh[d] = h;
                        }
                        __half2 hv; hv.x = __float2half(hh[0]); hv.y = __float2half(hh[1]);
                        *(__half2*)(slab + (long)b * HH + gb) = hv;
                    }
                }
                __threadfence();
                WG_BAR(2);
                if (ltid == 0) {
                    *cfl = (unsigned)(t + 1);        // partials consumed
                    atomicAdd(&g_prod[lay], 1u);     // step t published
                }
            }
        }
    } else {
        // ---------------- vocab projection ------------------------------------
        for (int t = 0; t < TT; ++t) {
            wg_wait(&g_prod[2], 32u * (unsigned)(t + 1), poller, barid);
            float acc[6][4] = {};
            if (wg == 0) {
                gemm_wg<2>(g_hA[2][t & 3], wbase, pitchWB, 0, abase, choff,
                           0, acc, tid, 1);
                #pragma unroll
                for (int j = 0; j < 2; ++j) {
                    #pragma unroll
                    for (int bs = 0; bs < 2; ++bs) {
                        const int b = b0 + 8 * bs;
                        #pragma unroll
                        for (int d = 0; d < 2; ++d) {
                            int v = vbase + j * 8 + (lane & 3) * 2 + d;
                            if (v < 65)
                                out[((long)b * TT + t) * 65 + v] =
                                    acc[j][bs * 2 + d] + __ldg(b_out + v);
                        }
                    }
                }
            } else {
                gemm_wg<3>(g_hA[2][t & 3], wbase, pitchWB, 0, abase, choff,
                           0, acc, tid, 2);
                #pragma unroll
                for (int bs = 0; bs < 2; ++bs) {
                    const int b = b0 + 8 * bs;
                    #pragma unroll
                    for (int d = 0; d < 2; ++d) {
                        int v = vbase + 16 + (lane & 3) * 2 + d;
                        if (v < 65)
                            out[((long)b * TT + t) * 65 + v] =
                                acc[2][bs * 2 + d] + __ldg(b_out + v);
                    }
                }
            }
            __syncthreads();
            if (tid == 0) atomicAdd(&g_cons[2], 1u);
        }
    }
}

// --------------------------------- launch ------------------------------------
extern "C" void kernel_launch(void* const* d_in, const int* in_sizes, int n_in,
                              void* d_out, int out_size) {
    const int*   x_seq = (const int*)  d_in[0];
    const float* emb   = (const float*)d_in[1];
    const float* w_ih  = (const float*)d_in[2];
    const float* w_hh  = (const float*)d_in[3];
    const float* b     = (const float*)d_in[4];
    const float* b_n   = (const float*)d_in[5];
    const float* w_out = (const float*)d_in[6];
    const float* b_out = (const float*)d_in[7];
    float* out = (float*)d_out;

    cudaFuncSetAttribute(k_main, cudaFuncAttributeMaxDynamicSharedMemorySize, SMEM_BYTES);

    k_zero<<<512, 256>>>();
    k_ig0<<<(65 * 1536 + 255) / 256, 256>>>(emb, w_ih, b);
    k_prepw<<<(int)((6L * 1536 * 512 + 255) / 256), 256>>>(w_ih, w_hh, w_out);
    k_main<<<NCTA, NTHR, SMEM_BYTES>>>(x_seq, b, b_n, b_out, out);
}

// round 14
// speedup vs baseline: 1.0029x; 1.0029x over previous
#include <cuda_runtime.h>
#include <cuda_fp16.h>
#include <cstdint>
#include <math.h>

#define BB 128
#define TT 1024
#define HH 512
#define NCTA 99
#define NTHR 512
#define RING 4

// smem: per-wg 3 A-buffers (128 x 144B) + persistent W + flags
#define ABYTES 18432
#define OFF_W  (2 * 3 * ABYTES)            // 110592
#define OFF_F  (OFF_W + 48 * 2064)         // 209664
#define SMEM_BYTES (OFF_F + 64)            // 209728

// ------------------------- persistent device state ---------------------------
__device__ float g_ig0[65 * 1536];                        // layer0 igates + bias
__device__ __align__(16) __half g_hA[3][RING][BB * HH];   // fp16 h ring [lay][slot]
__device__ __align__(16) __half g_wf16s[6][1536 * 512];   // fp16 weights [part]
__device__ unsigned g_prod[3];   // 32 * steps completed per layer
__device__ unsigned g_cons[3];   // external consumptions of layer l's output

// ------------------------------ helpers --------------------------------------
__device__ __forceinline__ float sigm(float x) { return 1.f / (1.f + __expf(-x)); }
__device__ __forceinline__ uint32_t smem_u32(const void* p) {
    uint32_t a;
    asm("{ .reg .u64 t; cvta.to.shared.u64 t, %1; cvt.u32.u64 %0, t; }" : "=r"(a) : "l"(p));
    return a;
}
__device__ __forceinline__ void ldsm4(uint32_t a, uint32_t& r0, uint32_t& r1,
                                      uint32_t& r2, uint32_t& r3) {
    asm volatile("ldmatrix.sync.aligned.m8n8.x4.shared.b16 {%0,%1,%2,%3}, [%4];"
                 : "=r"(r0), "=r"(r1), "=r"(r2), "=r"(r3) : "r"(a));
}
__device__ __forceinline__ void ldsm2(uint32_t a, uint32_t& r0, uint32_t& r1) {
    asm volatile("ldmatrix.sync.aligned.m8n8.x2.shared.b16 {%0,%1}, [%2];"
                 : "=r"(r0), "=r"(r1) : "r"(a));
}
__device__ __forceinline__ void mma4(float* d, uint32_t a0, uint32_t a1, uint32_t a2,
                                     uint32_t a3, uint32_t b0, uint32_t b1) {
    asm volatile("mma.sync.aligned.m16n8k16.row.col.f32.f16.f16.f32 "
                 "{%0,%1,%2,%3},{%4,%5,%6,%7},{%8,%9},{%0,%1,%2,%3};"
                 : "+f"(d[0]), "+f"(d[1]), "+f"(d[2]), "+f"(d[3])
                 : "r"(a0), "r"(a1), "r"(a2), "r"(a3), "r"(b0), "r"(b1));
}
__device__ __forceinline__ void cp16(uint32_t dst, const void* src) {
    asm volatile("cp.async.cg.shared.global [%0], [%1], 16;" :: "r"(dst), "l"(src));
}
#define CP_COMMIT() asm volatile("cp.async.commit_group;" ::: "memory")
#define CP_WAIT1()  asm volatile("cp.async.wait_group 1;" ::: "memory")
#define CP_WAIT0()  asm volatile("cp.async.wait_group 0;" ::: "memory")
#define WG_BAR(id)  asm volatile("bar.sync %0, 256;" :: "r"(id) : "memory")

// one poller per warpgroup; release via named barrier
__device__ __forceinline__ void wg_wait(volatile unsigned* p, unsigned target,
                                        bool poller, int barid) {
    if (poller) { while (*p < target) { } }
    WG_BAR(barid);
}

// ------------------------------ prep kernels ---------------------------------
__global__ void k_zero() {
    long i = (long)blockIdx.x * blockDim.x + threadIdx.x;
    __half* ph = &g_hA[0][0][0];
    long nh = 3L * RING * BB * HH;
    for (long j = i; j < nh; j += (long)gridDim.x * blockDim.x) ph[j] = __float2half(0.f);
    if (i < 3) { g_prod[i] = 0u; g_cons[i] = 0u; }
}

__global__ void k_ig0(const float* __restrict__ emb, const float* __restrict__ w_ih,
                      const float* __restrict__ bias) {
    int idx = blockIdx.x * blockDim.x + threadIdx.x;
    if (idx >= 65 * 1536) return;
    int tok = idx / 1536, j = idx - tok * 1536;
    const float* e = emb + tok * HH;
    const float* w = w_ih + (long)j * HH;
    float acc = bias[j];
    #pragma unroll 8
    for (int k = 0; k < HH; ++k) acc += e[k] * w[k];
    g_ig0[idx] = acc;
}

__global__ void k_prepw(const float* __restrict__ w_ih, const float* __restrict__ w_hh,
                        const float* __restrict__ w_out) {
    long idx = (long)blockIdx.x * 256 + threadIdx.x;     // 6 * 1536 * 512
    if (idx >= 6L * 1536 * 512) return;
    int k = (int)(idx & 511);
    long r = idx >> 9;
    int row = (int)(r % 1536);
    int part = (int)(r / 1536);
    float v = 0.f;
    if (part == 0)      v = w_hh[(long)row * 512 + k];
    else if (part == 1) v = w_ih[(1536L + row) * 512 + k];
    else if (part == 2) v = w_hh[(1536L + row) * 512 + k];
    else if (part == 3) v = w_ih[(2L * 1536 + row) * 512 + k];
    else if (part == 4) v = w_hh[(2L * 1536 + row) * 512 + k];
    else if (row < 65)  v = w_out[(long)row * 512 + k];
    g_wf16s[part][(long)row * 512 + k] = __float2half(v);
}

// ------------------------------ GEMM core ------------------------------------
// One warpgroup's K=512 GEMM: 8 chunks of 64 cols, private 3-buffer cp.async
// pipeline, per-wg named barrier. W persistent in smem (kcolB selects x/h part).
// MODE 0: 6 tiles rows 0-47 (3x ldsm4)         [L1/L2 split-K wg]
// MODE 1: 3 tiles rows rowbase..+24 (x4 + x2)  [L0 wg]
// MODE 2: 2 tiles rows 0-15 (x4)               [out wg0]
// MODE 3: 1 tile  rows 16-23 (x2)              [out wg1]
template <int MODE>
__device__ __forceinline__ void gemm_wg(
    const __half* __restrict__ A, uint32_t wbase, uint32_t pitchWB, uint32_t kcolB,
    uint32_t abase, int choff, int rowbase, float (&acc)[6][4], int tid, int barid)
{
    const int ltid = tid & 255;
    const int warpw = (tid >> 5) & 7;
    const int lane = tid & 31;
    const int lr = lane & 7, gq = lane >> 3;
    const uint32_t aoff = (uint32_t)((warpw * 16 + lr + (gq & 1) * 8) * 144
                                     + (gq >> 1) * 16);
    const uint32_t wr0 = (uint32_t)(rowbase + lr + (gq & 1) * 8) * pitchWB;
    const uint32_t wr1 = (uint32_t)(rowbase + 16 + lr + (gq & 1) * 8) * pitchWB;
    const uint32_t wr2 = (uint32_t)(rowbase + 32 + lr + (gq & 1) * 8) * pitchWB;
    const uint32_t wx2 = (uint32_t)(rowbase + 16 + lr) * pitchWB;
    const uint32_t k4 = (uint32_t)((gq >> 1) * 16);
    const uint32_t k2 = (uint32_t)(((lane >> 3) & 1) * 16);

    auto stage = [&](int j) {
        int cg = (j + choff) & 7;
        const __half* s = A + cg * 64;
        uint32_t dst = abase + (uint32_t)(j % 3) * ABYTES;
        #pragma unroll
        for (int i = 0; i < 4; ++i) {
            int e = ltid + i * 256;
            int rr = e >> 3, u = e & 7;
            cp16(dst + (uint32_t)(rr * 144 + u * 16), s + (long)rr * HH + u * 8);
        }
        CP_COMMIT();
    };

    stage(0); stage(1);
    #pragma unroll 1
    for (int j = 0; j < 8; ++j) {
        if (j == 7) CP_WAIT0(); else CP_WAIT1();
        WG_BAR(barid);
        if (j + 2 < 8) stage(j + 2);
        const int cg = (j + choff) & 7;
        const uint32_t kb = kcolB + (uint32_t)cg * 128;
        const uint32_t ab = abase + (uint32_t)(j % 3) * ABYTES;
        #pragma unroll
        for (int ks = 0; ks < 4; ++ks) {
            uint32_t a0, a1, a2, a3;
            ldsm4(ab + aoff + ks * 32, a0, a1, a2, a3);
            const uint32_t kk = kb + ks * 32;
            if (MODE == 0) {
                uint32_t b0, b1, b2, b3;
                ldsm4(wbase + wr0 + kk + k4, b0, b1, b2, b3);
                mma4(acc[0], a0, a1, a2, a3, b0, b2);
                mma4(acc[1], a0, a1, a2, a3, b1, b3);
                ldsm4(wbase + wr1 + kk + k4, b0, b1, b2, b3);
                mma4(acc[2], a0, a1, a2, a3, b0, b2);
                mma4(acc[3], a0, a1, a2, a3, b1, b3);
                ldsm4(wbase + wr2 + kk + k4, b0, b1, b2, b3);
                mma4(acc[4], a0, a1, a2, a3, b0, b2);
                mma4(acc[5], a0, a1, a2, a3, b1, b3);
            } else if (MODE == 1) {
                uint32_t b0, b1, b2, b3, c0, c1;
                ldsm4(wbase + wr0 + kk + k4, b0, b1, b2, b3);
                ldsm2(wbase + wx2 + kk + k2, c0, c1);
                mma4(acc[0], a0, a1, a2, a3, b0, b2);
                mma4(acc[1], a0, a1, a2, a3, b1, b3);
                mma4(acc[2], a0, a1, a2, a3, c0, c1);
            } else if (MODE == 2) {
                uint32_t b0, b1, b2, b3;
                ldsm4(wbase + wr0 + kk + k4, b0, b1, b2, b3);
                mma4(acc[0], a0, a1, a2, a3, b0, b2);
                mma4(acc[1], a0, a1, a2, a3, b1, b3);
            } else {
                uint32_t c0, c1;
                ldsm2(wbase + wx2 + kk + k2, c0, c1);
                mma4(acc[2], a0, a1, a2, a3, c0, c1);
            }
        }
    }
    WG_BAR(barid);    // all warps done; buffers reusable (partial overlay safe)
}

// ------------------------------- main kernel ---------------------------------
__global__ void __launch_bounds__(NTHR, 1) k_main(
    const int* __restrict__ x_seq,
    const float* __restrict__ bias, const float* __restrict__ b_n,
    const float* __restrict__ b_out, float* __restrict__ out)
{
    extern __shared__ unsigned char smem[];
    const uint32_t sbuf = smem_u32(smem);
    const uint32_t wbase = sbuf + OFF_W;
    volatile unsigned* pf = (volatile unsigned*)(smem + OFF_F);
    volatile unsigned* cfl = pf + 1;
    float* partial = (float*)smem;                       // overlays wg0's A bufs
    const int tid = threadIdx.x;
    const int wg = tid >> 8;
    const int ltid = tid & 255;
    const int lane = tid & 31, warpw = (tid >> 5) & 7;
    const int cta = blockIdx.x;
    const uint32_t abase = sbuf + (uint32_t)wg * (3 * ABYTES);
    const bool poller = (ltid == 0);
    const int barid = 1 + wg;

    // ---- role decode: 32 L0 | 32 L1 | 32 L2 | 3 out ----
    int role, lay = 0, n0 = 0, vbase = 0, rows_used, ktot, p0, p1;
    if (cta < 32) {
        role = 0; lay = 0; n0 = cta * 16; rows_used = 48; ktot = 512; p0 = 0; p1 = 0;
    } else if (cta < 64) {
        role = 1; lay = 1; n0 = (cta - 32) * 16; rows_used = 48; ktot = 1024; p0 = 1; p1 = 2;
    } else if (cta < 96) {
        role = 2; lay = 2; n0 = (cta - 64) * 16; rows_used = 48; ktot = 1024; p0 = 3; p1 = 4;
    } else {
        role = 3; lay = 3; vbase = (cta - 96) * 24; rows_used = 24; ktot = 512; p0 = 5; p1 = 5;
    }
    const int pitchWE = ktot + 8;
    const uint32_t pitchWB = (uint32_t)pitchWE * 2;
    const int choff = (cta * 5) & 7;
    const unsigned consC = (lay == 2) ? 3u : 32u;

    // ---- persistent W load + flag init ----
    {
        __half* ws = (__half*)(smem + OFF_W);
        for (int e = tid; e < rows_used * ktot; e += NTHR) {
            int r = e / ktot, k = e - r * ktot;
            int grow;
            if (role < 3) {
                int blk = r >> 3, w = blk / 3, gate = blk % 3;
                grow = gate * HH + n0 + w * 8 + (r & 7);
            } else {
                grow = vbase + r;
                if (grow > 64) grow = 0;
            }
            int part = (k < 512) ? p0 : p1;
            ws[r * pitchWE + k] = g_wf16s[part][(long)grow * 512 + (k & 511)];
        }
    }
    if (tid == 0) { *pf = 0u; *cfl = 0u; }
    __syncthreads();

    const int b0 = warpw * 16 + (lane >> 2);

    if (role == 0) {
        // ---------------- layer 0: both wgs N-split, identical schedule -------
        float hreg[4] = {0.f, 0.f, 0.f, 0.f};
        const int g0 = n0 + wg * 8 + (lane & 3) * 2;
        for (int t = 0; t < TT; ++t) {
            wg_wait(&g_prod[0], 32u * (unsigned)t, poller, barid);
            float acc[6][4] = {};
            gemm_wg<1>(g_hA[0][(t - 1) & 3], wbase, pitchWB, 0, abase, choff,
                       wg * 24, acc, tid, barid);
            if (t >= RING) wg_wait(&g_cons[0], 32u * (unsigned)(t - 3), poller, barid);
            __half* slab = g_hA[0][t & 3];
            #pragma unroll
            for (int bs = 0; bs < 2; ++bs) {
                const int b = b0 + 8 * bs;
                const int tok = __ldg(x_seq + (long)b * TT + t);
                const float* ig = g_ig0 + (long)tok * 1536;
                float hh[2];
                #pragma unroll
                for (int d = 0; d < 2; ++d) {
                    const int g = g0 + d, idx = bs * 2 + d;
                    float r = sigm(__ldg(ig + g) + acc[0][idx]);
                    float z = sigm(__ldg(ig + 512 + g) + acc[1][idx]);
                    float n = tanhf(__ldg(ig + 1024 + g)
                                    + r * (acc[2][idx] + __ldg(b_n + g)));
                    float h = n + z * (hreg[idx] - n);
                    hreg[idx] = h; hh[d] = h;
                }
                __half2 hv; hv.x = __float2half(hh[0]); hv.y = __float2half(hh[1]);
                *(__half2*)(slab + (long)b * HH + g0) = hv;
            }
            __threadfence();
            __syncthreads();
            if (tid == 0) atomicAdd(&g_prod[0], 1u);
        }
    } else if (role == 1 || role == 2) {
        if (wg == 0) {
            // ------------ x-part producer warpgroup --------------------------
            for (int t = 0; t < TT; ++t) {
                if (t >= 1) wg_wait(pf - 1 + 1 == pf ? cfl : cfl, (unsigned)t, poller, 1);
                wg_wait(&g_prod[lay - 1], 32u * (unsigned)(t + 1), poller, 1);
                float acc[6][4] = {};
                gemm_wg<0>(g_hA[lay - 1][t & 3], wbase, pitchWB, 0, abase, choff,
                           0, acc, tid, 1);
                if (tid == 0) atomicAdd(&g_cons[lay - 1], 1u);
                // publish partials into (now idle) own A-buffer region
                #pragma unroll
                for (int i = 0; i < 6; ++i)
                    *(float4*)(partial + ltid * 24 + i * 4) =
                        make_float4(acc[i][0], acc[i][1], acc[i][2], acc[i][3]);
                WG_BAR(1);
                if (tid == 0) *pf = (unsigned)(t + 1);
            }
        } else {
            // ------------ h-part + epilogue warpgroup ------------------------
            float hreg[8] = {0.f, 0.f, 0.f, 0.f, 0.f, 0.f, 0.f, 0.f};
            const float* bl = bias + (long)lay * 1536;
            const float* bnl = b_n + (long)lay * 512;
            for (int t = 0; t < TT; ++t) {
                wg_wait(&g_prod[lay], 32u * (unsigned)t, poller, 2);
                float accH[6][4] = {};
                gemm_wg<0>(g_hA[lay][(t - 1) & 3], wbase, pitchWB, 1024, abase, choff,
                           0, accH, tid, 2);
                wg_wait(pf, (unsigned)(t + 1), poller, 2);
                if (t >= RING) wg_wait(&g_cons[lay], consC * (unsigned)(t - 3), poller, 2);
                __half* slab = g_hA[lay][t & 3];
                const float* myp = partial + ltid * 24;
                #pragma unroll
                for (int cg = 0; cg < 2; ++cg) {
                    const int gb = n0 + cg * 8 + (lane & 3) * 2;
                    #pragma unroll
                    for (int bs = 0; bs < 2; ++bs) {
                        const int b = b0 + 8 * bs;
                        float hh[2];
                        #pragma unroll
                        for (int d = 0; d < 2; ++d) {
                            const int g = gb + d, idx = bs * 2 + d;
                            float ir = myp[(cg * 3 + 0) * 4 + idx] + __ldg(bl + g);
                            float iz = myp[(cg * 3 + 1) * 4 + idx] + __ldg(bl + 512 + g);
                            float in_ = myp[(cg * 3 + 2) * 4 + idx] + __ldg(bl + 1024 + g);
                            float r = sigm(ir + accH[cg * 3 + 0][idx]);
                            float z = sigm(iz + accH[cg * 3 + 1][idx]);
                            float n = tanhf(in_ + r * (accH[cg * 3 + 2][idx] + __ldg(bnl + g)));
                            float h = n + z * (hreg[cg * 4 + idx] - n);
                            hreg[cg * 4 + idx] = h; hh[d] = h;
                        }
                        __half2 hv; hv.x = __float2half(hh[0]); hv.y = __float2half(hh[1]);
                        *(__half2*)(slab + (long)b * HH + gb) = hv;
                    }
                }
                __threadfence();
                WG_BAR(2);
                if (ltid == 0) {
                    *cfl = (unsigned)(t + 1);        // partials consumed
                    atomicAdd(&g_prod[lay], 1u);     // step t published
                }
            }
        }
    } else {
        // ---------------- vocab projection ------------------------------------
        for (int t = 0; t < TT; ++t) {
            wg_wait(&g_prod[2], 32u * (unsigned)(t + 1), poller, barid);
            float acc[6][4] = {};
            if (wg == 0) {
                gemm_wg<2>(g_hA[2][t & 3], wbase, pitchWB, 0, abase, choff,
                           0, acc, tid, 1);
                #pragma unroll
                for (int j = 0; j < 2; ++j) {
                    #pragma unroll
                    for (int bs = 0; bs < 2; ++bs) {
                        const int b = b0 + 8 * bs;
                        #pragma unroll
                        for (int d = 0; d < 2; ++d) {
                            int v = vbase + j * 8 + (lane & 3) * 2 + d;
                            if (v < 65)
                                out[((long)b * TT + t) * 65 + v] =
                                    acc[j][bs * 2 + d] + __ldg(b_out + v);
                        }
                    }
                }
            } else {
                gemm_wg<3>(g_hA[2][t & 3], wbase, pitchWB, 0, abase, choff,
                           0, acc, tid, 2);
                #pragma unroll
                for (int bs = 0; bs < 2; ++bs) {
                    const int b = b0 + 8 * bs;
                    #pragma unroll
                    for (int d = 0; d < 2; ++d) {
                        int v = vbase + 16 + (lane & 3) * 2 + d;
                        if (v < 65)
                            out[((long)b * TT + t) * 65 + v] =
                                acc[2][bs * 2 + d] + __ldg(b_out + v);
                    }
                }
            }
            __syncthreads();
            if (tid == 0) atomicAdd(&g_cons[2], 1u);
        }
    }
}

// --------------------------------- launch ------------------------------------
extern "C" void kernel_launch(void* const* d_in, const int* in_sizes, int n_in,
                              void* d_out, int out_size) {
    const int*   x_seq = (const int*)  d_in[0];
    const float* emb   = (const float*)d_in[1];
    const float* w_ih  = (const float*)d_in[2];
    const float* w_hh  = (const float*)d_in[3];
    const float* b     = (const float*)d_in[4];
    const float* b_n   = (const float*)d_in[5];
    const float* w_out = (const float*)d_in[6];
    const float* b_out = (const float*)d_in[7];
    float* out = (float*)d_out;

    cudaFuncSetAttribute(k_main, cudaFuncAttributeMaxDynamicSharedMemorySize, SMEM_BYTES);

    k_zero<<<512, 256>>>();
    k_ig0<<<(65 * 1536 + 255) / 256, 256>>>(emb, w_ih, b);
    k_prepw<<<(int)((6L * 1536 * 512 + 255) / 256), 256>>>(w_ih, w_hh, w_out);
    k_main<<<NCTA, NTHR, SMEM_BYTES>>>(x_seq, b, b_n, b_out, out);
}